// round 16
// baseline (speedup 1.0000x reference)
#include <cuda_runtime.h>
#include <cuda_bf16.h>
#include <cuda_fp16.h>
#include <cstdint>
#include <cstring>

// ---------------------------------------------------------------------------
// SpatialWindowSelfAttention on GB300 (sm_103a), b=2, h=w=256, C=256,
// heads=8, head_dim=32, window 8x8 (ws=64).
//
//  1) split_weights_kernel : Wqkv/Wp fp32 -> (hi, lo) bf16
//  2) split_x_kernel       : x fp32 -> (hi, lo) bf16
//  3) tc_gemm_kernel (QKV) : tcgen05 SS bf16x3, double-buffered cp.async
//                            pipeline; epilogue emits qkv as fp16 hi/lo
//  4) window_attn_kernel   : mma.sync fp16x2 attention; q/k loaded by
//                            cp.async straight into ldmatrix layout
//  5) tc_gemm_kernel (proj): fp32 epilogue -> d_out
// ---------------------------------------------------------------------------

#define K_DIM 256

// Scratch (b=2 fixed by the problem instance)
__device__ __half g_qkvh[131072ull * 768];          // 192 MiB
__device__ __half g_qkvl[131072ull * 768];          // 192 MiB
__device__ __nv_bfloat16 g_xh[131072ull * 256];     // 64 MiB
__device__ __nv_bfloat16 g_xl[131072ull * 256];
__device__ __nv_bfloat16 g_yh[131072ull * 256];
__device__ __nv_bfloat16 g_yl[131072ull * 256];
__device__ __nv_bfloat16 g_wqkv_h[768 * 256];
__device__ __nv_bfloat16 g_wqkv_l[768 * 256];
__device__ __nv_bfloat16 g_wp_h  [256 * 256];
__device__ __nv_bfloat16 g_wp_l  [256 * 256];

// ------------------------------ helpers ------------------------------------
__device__ __forceinline__ uint32_t smem_u32(const void* p) {
    uint32_t a;
    asm("{ .reg .u64 t; cvta.to.shared.u64 t, %1; cvt.u32.u64 %0, t; }"
        : "=r"(a) : "l"(p));
    return a;
}

__device__ __forceinline__ void ldsm_x4(uint32_t* r, uint32_t addr) {
    asm volatile("ldmatrix.sync.aligned.m8n8.x4.shared.b16 {%0,%1,%2,%3}, [%4];"
        : "=r"(r[0]), "=r"(r[1]), "=r"(r[2]), "=r"(r[3]) : "r"(addr));
}

__device__ __forceinline__ void mma16816h(float* c, const uint32_t* a,
                                          const uint32_t* b) {
    asm volatile(
        "mma.sync.aligned.m16n8k16.row.col.f32.f16.f16.f32 "
        "{%0,%1,%2,%3}, {%4,%5,%6,%7}, {%8,%9}, {%0,%1,%2,%3};"
        : "+f"(c[0]), "+f"(c[1]), "+f"(c[2]), "+f"(c[3])
        : "r"(a[0]), "r"(a[1]), "r"(a[2]), "r"(a[3]), "r"(b[0]), "r"(b[1]));
}

__device__ __forceinline__ void cp_async16(uint32_t saddr, const void* g) {
    asm volatile("cp.async.cg.shared.global [%0], [%1], 16;"
        :: "r"(saddr), "l"(g));
}
#define CP_COMMIT() asm volatile("cp.async.commit_group;" ::: "memory")
#define CP_WAIT0()  asm volatile("cp.async.wait_group 0;"  ::: "memory")

__device__ __forceinline__ void split2(float x, float y,
                                       uint32_t& h, uint32_t& l) {
    __nv_bfloat162 h2 = __floats2bfloat162_rn(x, y);
    float2 g = __bfloat1622float2(h2);
    __nv_bfloat162 l2 = __floats2bfloat162_rn(x - g.x, y - g.y);
    memcpy(&h, &h2, 4);
    memcpy(&l, &l2, 4);
}

__device__ __forceinline__ void split2h(float x, float y,
                                        uint32_t& h, uint32_t& l) {
    __half2 h2 = __floats2half2_rn(x, y);
    float2 g = __half22float2(h2);
    __half2 l2 = __floats2half2_rn(x - g.x, y - g.y);
    memcpy(&h, &h2, 4);
    memcpy(&l, &l2, 4);
}

#define SW128(o) ((o) ^ (((o) >> 3) & 0x70))

// ---------------------------------------------------------------------------
// Splits
// ---------------------------------------------------------------------------
__global__ void split_weights_kernel(const float* __restrict__ wqkv,
                                     const float* __restrict__ wp) {
    int i = blockIdx.x * blockDim.x + threadIdx.x;
    if (i < 768 * 256) {
        float f = wqkv[i];
        __nv_bfloat16 h = __float2bfloat16(f);
        g_wqkv_h[i] = h;
        g_wqkv_l[i] = __float2bfloat16(f - __bfloat162float(h));
    }
    if (i < 256 * 256) {
        float f = wp[i];
        __nv_bfloat16 h = __float2bfloat16(f);
        g_wp_h[i] = h;
        g_wp_l[i] = __float2bfloat16(f - __bfloat162float(h));
    }
}

__global__ void split_x_kernel(const float* __restrict__ x) {
    long i = (long)(blockIdx.x * blockDim.x + threadIdx.x) * 4;
    float4 v = *(const float4*)(x + i);
    uint2 h, l;
    split2(v.x, v.y, h.x, l.x);
    split2(v.z, v.w, h.y, l.y);
    *(uint2*)(g_xh + i) = h;
    *(uint2*)(g_xl + i) = l;
}

// ---------------------------------------------------------------------------
// tcgen05 feature-gated GEMM, double-buffered.
// Block tile 128(M) x 256(N), K=256 in 4 chunks of 64. Two 96KB smem stages
// (193KB total -> 1 CTA/SM): cp.async of chunk c+1 overlaps tcgen05 MMAs of
// chunk c; lag-1 mbarrier protects buffer reuse.
// Epilogue: fp32 (+bias) OR fp16 hi/lo split (for the QKV pass).
// ---------------------------------------------------------------------------
#define TCGEMM_OK (!defined(__CUDA_ARCH__) || defined(__CUDA_ARCH_FEAT_SM103_ALL))

#define SM2_TMPTR 0
#define SM2_MBAR  8
#define SM2_BUF0  1024
#define SM2_BUFSZ 98304
#define B_AH 0
#define B_AL 16384
#define B_BH 32768
#define B_BL 65536
#define SM2_TOTAL (1024 + 2 * SM2_BUFSZ)   // 197632 B

static constexpr uint64_t DESC_BASE_SW128 =
    (uint64_t(2) << 61) | (uint64_t(1) << 46) | (uint64_t(64) << 32) | (uint64_t(1) << 16);

// idesc kind::f16: F32 accum, BF16 A/B, N=256, M=128 (formula verified vs 0x8080490)
static constexpr uint32_t TC_IDESC =
    (1u << 4) | (1u << 7) | (1u << 10) | (32u << 17) | (8u << 24);

#if TCGEMM_OK
__device__ __forceinline__ uint32_t elect_one_pred() {
    uint32_t pred;
    asm volatile(
        "{\n\t.reg .pred p;\n\telect.sync _|p, 0xFFFFFFFF;\n\t"
        "selp.b32 %0, 1, 0, p;\n\t}" : "=r"(pred));
    return pred;
}

__device__ __forceinline__ void mma_f16_ss(uint32_t d, uint64_t a, uint64_t b,
                                           uint32_t idesc, uint32_t en) {
    asm volatile(
        "{\n\t.reg .pred p;\n\tsetp.ne.u32 p, %5, 0;\n\t"
        "tcgen05.mma.cta_group::1.kind::f16 [%0], %1, %2, %3, {%4, %4, %4, %4}, p;\n\t}"
        :: "r"(d), "l"(a), "l"(b), "r"(idesc), "r"(0u), "r"(en) : "memory");
}

#define MBAR_WAIT(mbar, parity) do {                                          \
    uint32_t _done;                                                           \
    asm volatile(                                                             \
        "{\n\t.reg .pred p;\n\t"                                              \
        "mbarrier.try_wait.parity.acquire.cta.shared::cta.b64 p, [%1], %2;\n\t" \
        "selp.b32 %0, 1, 0, p;\n\t}"                                          \
        : "=r"(_done) : "r"((uint32_t)(mbar)), "r"((uint32_t)(parity)) : "memory"); \
    if (!_done) {                                                             \
        asm volatile(                                                         \
            "{\n\t.reg .pred P1;\n\t"                                         \
            "WL_%=:\n\t"                                                      \
            "mbarrier.try_wait.parity.acquire.cta.shared::cta.b64 P1, [%0], %1, 0x989680;\n\t" \
            "@P1 bra.uni WD_%=;\n\t"                                          \
            "bra.uni WL_%=;\n\t"                                              \
            "WD_%=:\n\t}"                                                     \
            :: "r"((uint32_t)(mbar)), "r"((uint32_t)(parity)) : "memory");    \
    }                                                                         \
} while (0)
#endif

__global__ __launch_bounds__(256, 1) void tc_gemm_kernel(
    const __nv_bfloat16* __restrict__ Ah, const __nv_bfloat16* __restrict__ Al,
    const __nv_bfloat16* __restrict__ Wh, const __nv_bfloat16* __restrict__ Wl,
    const float* __restrict__ bias, float* __restrict__ C,
    __half* __restrict__ Ch, __half* __restrict__ Cl, int Ntot) {
#if TCGEMM_OK
    extern __shared__ char smem[];
    const uint32_t sb = smem_u32(smem);
    const int tid  = threadIdx.x;
    const int lane = tid & 31;
    const int w    = tid >> 5;
    const long rowBase = (long)blockIdx.y * 128;
    const int  colBase = blockIdx.x * 256;

    if (w == 0) {
        asm volatile(
            "tcgen05.alloc.cta_group::1.sync.aligned.shared::cta.b32 [%0], %1;"
            :: "r"(sb + SM2_TMPTR), "r"(256u) : "memory");
        asm volatile("tcgen05.relinquish_alloc_permit.cta_group::1.sync.aligned;");
    }
    if (tid == 0)
        asm volatile("mbarrier.init.shared.b64 [%0], %1;"
            :: "r"(sb + SM2_MBAR), "r"(1u) : "memory");
    __syncthreads();

    uint32_t tmem;
    asm volatile("ld.shared.b32 %0, [%1];" : "=r"(tmem) : "r"(sb + SM2_TMPTR));

#define GLOAD2(cc, ss) do {                                                   \
    const int k0 = (cc) * 64;                                                 \
    const uint32_t base = sb + SM2_BUF0 + (ss) * SM2_BUFSZ;                   \
    _Pragma("unroll")                                                         \
    for (int i = 0; i < 4; i++) {                                             \
        int li = tid + i * 256;                                               \
        int row = li >> 3, oct = li & 7;                                      \
        uint32_t so = SW128((uint32_t)(row * 128 + oct * 16));                \
        long ga = (rowBase + row) * K_DIM + k0 + oct * 8;                     \
        cp_async16(base + B_AH + so, Ah + ga);                                \
        cp_async16(base + B_AL + so, Al + ga);                                \
    }                                                                         \
    _Pragma("unroll")                                                         \
    for (int i = 0; i < 8; i++) {                                             \
        int li = tid + i * 256;                                               \
        int row = li >> 3, oct = li & 7;                                      \
        uint32_t so = SW128((uint32_t)(row * 128 + oct * 16));                \
        long gb = (long)(colBase + row) * K_DIM + k0 + oct * 8;               \
        cp_async16(base + B_BH + so, Wh + gb);                                \
        cp_async16(base + B_BL + so, Wl + gb);                                \
    }                                                                         \
} while (0)

    GLOAD2(0, 0); CP_COMMIT();

    for (int c = 0; c < 4; c++) {
        const int s = c & 1;
        CP_WAIT0();
        __syncthreads();
        asm volatile("fence.proxy.async.shared::cta;" ::: "memory");

        if (w == 0 && elect_one_pred()) {
            const uint32_t base = sb + SM2_BUF0 + s * SM2_BUFSZ;
            uint64_t ah = DESC_BASE_SW128 | (((uint64_t)(base + B_AH) >> 4) & 0x3FFF);
            uint64_t al = DESC_BASE_SW128 | (((uint64_t)(base + B_AL) >> 4) & 0x3FFF);
            uint64_t bh = DESC_BASE_SW128 | (((uint64_t)(base + B_BH) >> 4) & 0x3FFF);
            uint64_t bl = DESC_BASE_SW128 | (((uint64_t)(base + B_BL) >> 4) & 0x3FFF);
#pragma unroll
            for (int k = 0; k < 4; k++) {
                uint32_t en0 = (c == 0 && k == 0) ? 0u : 1u;
                mma_f16_ss(tmem, ah + k * 2, bh + k * 2, TC_IDESC, en0);
                mma_f16_ss(tmem, ah + k * 2, bl + k * 2, TC_IDESC, 1u);
                mma_f16_ss(tmem, al + k * 2, bh + k * 2, TC_IDESC, 1u);
            }
            asm volatile(
                "tcgen05.commit.cta_group::1.mbarrier::arrive::one.shared::cluster.b64 [%0];"
                :: "r"(sb + SM2_MBAR) : "memory");
        }

        if (c < 3) {
            // Buffer s^1 is free only once chunk c-1's MMAs (which read it)
            // completed. Load of chunk c+1 then overlaps MMAs of chunk c.
            if (c >= 1) MBAR_WAIT(sb + SM2_MBAR, (c - 1) & 1);
            GLOAD2(c + 1, s ^ 1);
            CP_COMMIT();
        }
    }

    MBAR_WAIT(sb + SM2_MBAR, 1);     // chunk 3 done
    asm volatile("tcgen05.fence::after_thread_sync;" ::: "memory");

    // Epilogue: 8 warps; subpartition sp = w&3 (rows sp*32+lane),
    // column half chh = (w>>2)*128, 4 segments of 32 cols.
    {
        const int sp  = w & 3;
        const int chh = (w >> 2) * 128;
        const long row = rowBase + sp * 32 + lane;
#pragma unroll
        for (int seg = 0; seg < 4; seg++) {
            uint32_t r[32];
            asm volatile(
                "tcgen05.ld.sync.aligned.32x32b.x32.b32 "
                "{%0, %1, %2, %3, %4, %5, %6, %7, "
                " %8, %9, %10, %11, %12, %13, %14, %15, "
                " %16, %17, %18, %19, %20, %21, %22, %23, "
                " %24, %25, %26, %27, %28, %29, %30, %31}, [%32];"
                : "=r"(r[0]),  "=r"(r[1]),  "=r"(r[2]),  "=r"(r[3]),
                  "=r"(r[4]),  "=r"(r[5]),  "=r"(r[6]),  "=r"(r[7]),
                  "=r"(r[8]),  "=r"(r[9]),  "=r"(r[10]), "=r"(r[11]),
                  "=r"(r[12]), "=r"(r[13]), "=r"(r[14]), "=r"(r[15]),
                  "=r"(r[16]), "=r"(r[17]), "=r"(r[18]), "=r"(r[19]),
                  "=r"(r[20]), "=r"(r[21]), "=r"(r[22]), "=r"(r[23]),
                  "=r"(r[24]), "=r"(r[25]), "=r"(r[26]), "=r"(r[27]),
                  "=r"(r[28]), "=r"(r[29]), "=r"(r[30]), "=r"(r[31])
                : "r"(tmem + chh + seg * 32));
            asm volatile("tcgen05.wait::ld.sync.aligned;" ::: "memory");
            const int colb = colBase + chh + seg * 32;
            if (Ch) {
                __half* oh = Ch + row * Ntot + colb;
                __half* ol = Cl + row * Ntot + colb;
#pragma unroll
                for (int j = 0; j < 8; j++) {
                    float4 bv = __ldg((const float4*)(bias + colb + j * 4));
                    float ox = __uint_as_float(r[j * 4 + 0]) + bv.x;
                    float oy = __uint_as_float(r[j * 4 + 1]) + bv.y;
                    float oz = __uint_as_float(r[j * 4 + 2]) + bv.z;
                    float ow = __uint_as_float(r[j * 4 + 3]) + bv.w;
                    uint32_t h0, l0, h1, l1;
                    split2h(ox, oy, h0, l0);
                    split2h(oz, ow, h1, l1);
                    uint2 uh; uh.x = h0; uh.y = h1;
                    uint2 ul; ul.x = l0; ul.y = l1;
                    *(uint2*)(oh + j * 4) = uh;
                    *(uint2*)(ol + j * 4) = ul;
                }
            } else {
                float* cp = C + row * Ntot + colb;
#pragma unroll
                for (int j = 0; j < 8; j++) {
                    float4 bv = __ldg((const float4*)(bias + colb + j * 4));
                    float4 o;
                    o.x = __uint_as_float(r[j * 4 + 0]) + bv.x;
                    o.y = __uint_as_float(r[j * 4 + 1]) + bv.y;
                    o.z = __uint_as_float(r[j * 4 + 2]) + bv.z;
                    o.w = __uint_as_float(r[j * 4 + 3]) + bv.w;
                    *(float4*)(cp + j * 4) = o;
                }
            }
        }
    }
    __syncthreads();
    if (tid == 0)
        asm volatile("mbarrier.inval.shared.b64 [%0];" :: "r"(sb + SM2_MBAR) : "memory");
    if (w == 0)
        asm volatile("tcgen05.dealloc.cta_group::1.sync.aligned.b32 %0, %1;"
            :: "r"(tmem), "r"(256u));
#endif  // TCGEMM_OK
}

// ---------------------------------------------------------------------------
// Tensor-core window attention. qkv arrives as fp16 hi/lo, so Q/K tiles are
// pure cp.async into the ldmatrix layout [tok][QK_STR]; V is scalar-transposed
// to [d][VT_STR]. Scale 1/sqrt(32) applied post-QK on fragments.
// ---------------------------------------------------------------------------
#define QK_STR 40
#define VT_STR 72

__global__ __launch_bounds__(128) void window_attn_kernel(
    const __half* __restrict__ qkvh, const __half* __restrict__ qkvl,
    const float* __restrict__ bias_table,
    __nv_bfloat16* __restrict__ yh, __nv_bfloat16* __restrict__ yl) {
    const int head = blockIdx.x & 7;
    const int wi   = blockIdx.x >> 3;
    const int bimg = wi >> 10;
    const int widx = wi & 1023;
    const int wr   = widx >> 5;
    const int wc   = widx & 31;

    __shared__ __half qh_s[64 * QK_STR];
    __shared__ __half ql_s[64 * QK_STR];
    __shared__ __half kh_s[64 * QK_STR];
    __shared__ __half kl_s[64 * QK_STR];
    __shared__ __half vh_s[32 * VT_STR];
    __shared__ __half vl_s[32 * VT_STR];
    __shared__ float  bias_s[225];

    const int tid  = threadIdx.x;
    const int lane = tid & 31;
    const int w    = tid >> 5;

    const uint32_t qh_b = smem_u32(qh_s), ql_b = smem_u32(ql_s);
    const uint32_t kh_b = smem_u32(kh_s), kl_b = smem_u32(kl_s);

    // Q/K via cp.async: 256 (tok, 16B-chunk) units, 2 per thread, 4 tensors.
#pragma unroll
    for (int i = 0; i < 2; i++) {
        int u   = tid + i * 128;
        int tok = u >> 2;
        int c4  = u & 3;
        long grow = (long)bimg * 65536 + (long)(wr * 8 + (tok >> 3)) * 256 + wc * 8 + (tok & 7);
        long gb = grow * 768 + head * 32 + c4 * 8;
        uint32_t dst = (uint32_t)(tok * (QK_STR * 2) + c4 * 16);
        cp_async16(qh_b + dst, qkvh + gb);
        cp_async16(ql_b + dst, qkvl + gb);
        cp_async16(kh_b + dst, qkvh + gb + 256);
        cp_async16(kl_b + dst, qkvl + gb + 256);
    }
    CP_COMMIT();

    for (int i = tid; i < 225; i += 128) bias_s[i] = bias_table[i * 8 + head];

    // V: scalar transpose into [d][tok]; 256 (tok, 8-dim) units, 2 per thread.
#pragma unroll
    for (int i = 0; i < 2; i++) {
        int u   = tid + i * 128;
        int tok = u >> 2;
        int dg  = (u & 3) * 8;
        long grow = (long)bimg * 65536 + (long)(wr * 8 + (tok >> 3)) * 256 + wc * 8 + (tok & 7);
        long gb = grow * 768 + head * 32 + 512 + dg;
        uint4 hv = *(const uint4*)(qkvh + gb);
        uint4 lv = *(const uint4*)(qkvl + gb);
        const __half* hp = (const __half*)&hv;
        const __half* lp = (const __half*)&lv;
#pragma unroll
        for (int j = 0; j < 8; j++) {
            vh_s[(dg + j) * VT_STR + tok] = hp[j];
            vl_s[(dg + j) * VT_STR + tok] = lp[j];
        }
    }
    CP_WAIT0();
    __syncthreads();

    const int a_r = lane & 15;
    const int a_c = (lane >> 4) * 8;
    const int b_n = (lane & 7) + ((lane >> 4) << 3);
    const int b_k = ((lane >> 3) & 1) * 8;

    const uint32_t vh_b = smem_u32(vh_s), vl_b = smem_u32(vl_s);
    const int wrow = w * 16;

    // ---- QK: S (16 x 64) fragments ----
    uint32_t qhf[2][4], qlf[2][4];
#pragma unroll
    for (int ks = 0; ks < 2; ks++) {
        uint32_t off = (uint32_t)(((wrow + a_r) * QK_STR + ks * 16 + a_c) * 2);
        ldsm_x4(qhf[ks], qh_b + off);
        ldsm_x4(qlf[ks], ql_b + off);
    }

    float sacc[8][4];
#pragma unroll
    for (int nt = 0; nt < 8; nt++)
#pragma unroll
        for (int j = 0; j < 4; j++) sacc[nt][j] = 0.0f;

#pragma unroll
    for (int nt2 = 0; nt2 < 4; nt2++) {
#pragma unroll
        for (int ks = 0; ks < 2; ks++) {
            uint32_t off = (uint32_t)(((nt2 * 16 + b_n) * QK_STR + ks * 16 + b_k) * 2);
            uint32_t khf[4], klf[4];
            ldsm_x4(khf, kh_b + off);
            ldsm_x4(klf, kl_b + off);
            mma16816h(sacc[nt2 * 2],     qhf[ks], khf);
            mma16816h(sacc[nt2 * 2 + 1], qhf[ks], khf + 2);
            mma16816h(sacc[nt2 * 2],     qhf[ks], klf);
            mma16816h(sacc[nt2 * 2 + 1], qhf[ks], klf + 2);
            mma16816h(sacc[nt2 * 2],     qlf[ks], khf);
            mma16816h(sacc[nt2 * 2 + 1], qlf[ks], khf + 2);
        }
    }

    // ---- scale + bias + softmax on fragments ----
    const float scale = 0.17677669529663687f;   // 1/sqrt(32)
    const int fr  = lane >> 2;
    const int fc  = (lane & 3) * 2;
    const int qi0 = wrow + fr;
    const int qi1 = qi0 + 8;

    float m0 = -1e30f, m1 = -1e30f;
#pragma unroll
    for (int nt = 0; nt < 8; nt++) {
        int ki = nt * 8 + fc;
        int q0r = qi0 >> 3, q0c = qi0 & 7, q1r = qi1 >> 3, q1c = qi1 & 7;
        int k0r = ki >> 3,  k0c = ki & 7,  k1r = (ki + 1) >> 3, k1c = (ki + 1) & 7;
        sacc[nt][0] = fmaf(sacc[nt][0], scale, bias_s[(q0r - k0r + 7) * 15 + (q0c - k0c + 7)]);
        sacc[nt][1] = fmaf(sacc[nt][1], scale, bias_s[(q0r - k1r + 7) * 15 + (q0c - k1c + 7)]);
        sacc[nt][2] = fmaf(sacc[nt][2], scale, bias_s[(q1r - k0r + 7) * 15 + (q1c - k0c + 7)]);
        sacc[nt][3] = fmaf(sacc[nt][3], scale, bias_s[(q1r - k1r + 7) * 15 + (q1c - k1c + 7)]);
        m0 = fmaxf(m0, fmaxf(sacc[nt][0], sacc[nt][1]));
        m1 = fmaxf(m1, fmaxf(sacc[nt][2], sacc[nt][3]));
    }
    m0 = fmaxf(m0, __shfl_xor_sync(0xffffffffu, m0, 1));
    m0 = fmaxf(m0, __shfl_xor_sync(0xffffffffu, m0, 2));
    m1 = fmaxf(m1, __shfl_xor_sync(0xffffffffu, m1, 1));
    m1 = fmaxf(m1, __shfl_xor_sync(0xffffffffu, m1, 2));

    float s0 = 0.0f, s1 = 0.0f;
#pragma unroll
    for (int nt = 0; nt < 8; nt++) {
        sacc[nt][0] = __expf(sacc[nt][0] - m0);
        sacc[nt][1] = __expf(sacc[nt][1] - m0);
        sacc[nt][2] = __expf(sacc[nt][2] - m1);
        sacc[nt][3] = __expf(sacc[nt][3] - m1);
        s0 += sacc[nt][0] + sacc[nt][1];
        s1 += sacc[nt][2] + sacc[nt][3];
    }
    s0 += __shfl_xor_sync(0xffffffffu, s0, 1);
    s0 += __shfl_xor_sync(0xffffffffu, s0, 2);
    s1 += __shfl_xor_sync(0xffffffffu, s1, 1);
    s1 += __shfl_xor_sync(0xffffffffu, s1, 2);
    const float inv0 = 1.0f / s0;
    const float inv1 = 1.0f / s1;

    // ---- P fragments (fp16 hi/lo) from C fragments ----
    uint32_t phf[4][4], plf[4][4];
#pragma unroll
    for (int kk = 0; kk < 4; kk++) {
        const int t0 = kk * 2, t1 = kk * 2 + 1;
        split2h(sacc[t0][0] * inv0, sacc[t0][1] * inv0, phf[kk][0], plf[kk][0]);
        split2h(sacc[t0][2] * inv1, sacc[t0][3] * inv1, phf[kk][1], plf[kk][1]);
        split2h(sacc[t1][0] * inv0, sacc[t1][1] * inv0, phf[kk][2], plf[kk][2]);
        split2h(sacc[t1][2] * inv1, sacc[t1][3] * inv1, phf[kk][3], plf[kk][3]);
    }

    // ---- PV ----
    float oacc[4][4];
#pragma unroll
    for (int nt = 0; nt < 4; nt++)
#pragma unroll
        for (int j = 0; j < 4; j++) oacc[nt][j] = 0.0f;

#pragma unroll
    for (int kk = 0; kk < 4; kk++) {
#pragma unroll
        for (int nt2 = 0; nt2 < 2; nt2++) {
            uint32_t off = (uint32_t)(((nt2 * 16 + b_n) * VT_STR + kk * 16 + b_k) * 2);
            uint32_t vhf[4], vlf[4];
            ldsm_x4(vhf, vh_b + off);
            ldsm_x4(vlf, vl_b + off);
            mma16816h(oacc[nt2 * 2],     phf[kk], vhf);
            mma16816h(oacc[nt2 * 2 + 1], phf[kk], vhf + 2);
            mma16816h(oacc[nt2 * 2],     phf[kk], vlf);
            mma16816h(oacc[nt2 * 2 + 1], phf[kk], vlf + 2);
            mma16816h(oacc[nt2 * 2],     plf[kk], vhf);
            mma16816h(oacc[nt2 * 2 + 1], plf[kk], vhf + 2);
        }
    }

    // ---- write y as bf16 hi/lo ----
    {
        long row0 = (long)bimg * 65536 + (long)(wr * 8 + (qi0 >> 3)) * 256 + wc * 8 + (qi0 & 7);
        long row1 = (long)bimg * 65536 + (long)(wr * 8 + (qi1 >> 3)) * 256 + wc * 8 + (qi1 & 7);
#pragma unroll
        for (int nt = 0; nt < 4; nt++) {
            int d = nt * 8 + fc;
            long off0 = row0 * 256 + head * 32 + d;
            long off1 = row1 * 256 + head * 32 + d;
            uint32_t hq, lq;
            split2(oacc[nt][0], oacc[nt][1], hq, lq);
            *(uint32_t*)(yh + off0) = hq;
            *(uint32_t*)(yl + off0) = lq;
            split2(oacc[nt][2], oacc[nt][3], hq, lq);
            *(uint32_t*)(yh + off1) = hq;
            *(uint32_t*)(yl + off1) = lq;
        }
    }
}

extern "C" void kernel_launch(void* const* d_in, const int* in_sizes, int n_in,
                              void* d_out, int out_size) {
    const float* x          = (const float*)d_in[0];
    const float* wqkv_w     = (const float*)d_in[3];
    const float* wqkv_b     = (const float*)d_in[4];
    const float* wp_w       = (const float*)d_in[5];
    const float* wp_b       = (const float*)d_in[6];
    const float* bias_table = (const float*)d_in[7];
    float* out = (float*)d_out;

    const int M = in_sizes[0] / K_DIM;         // 131072 rows

    __half *qkvh, *qkvl;
    __nv_bfloat16 *xh, *xl, *yh, *yl, *wqh, *wql, *wph, *wpl;
    cudaGetSymbolAddress((void**)&qkvh, g_qkvh);
    cudaGetSymbolAddress((void**)&qkvl, g_qkvl);
    cudaGetSymbolAddress((void**)&xh, g_xh);
    cudaGetSymbolAddress((void**)&xl, g_xl);
    cudaGetSymbolAddress((void**)&yh, g_yh);
    cudaGetSymbolAddress((void**)&yl, g_yl);
    cudaGetSymbolAddress((void**)&wqh, g_wqkv_h);
    cudaGetSymbolAddress((void**)&wql, g_wqkv_l);
    cudaGetSymbolAddress((void**)&wph, g_wp_h);
    cudaGetSymbolAddress((void**)&wpl, g_wp_l);

    cudaFuncSetAttribute(tc_gemm_kernel,
                         cudaFuncAttributeMaxDynamicSharedMemorySize, SM2_TOTAL);

    // 0) splits
    split_weights_kernel<<<768, 256>>>(wqkv_w, wp_w);
    split_x_kernel<<<(M * K_DIM) / (4 * 256), 256>>>(x);

    // 1) QKV projection -> fp16 hi/lo qkv
    {
        dim3 grid(3, M / 128);
        tc_gemm_kernel<<<grid, 256, SM2_TOTAL>>>(xh, xl, wqh, wql, wqkv_b,
                                                 nullptr, qkvh, qkvl, 768);
    }

    // 2) Window attention
    {
        int nblocks = (M / 65536) * 1024 * 8;
        window_attn_kernel<<<nblocks, 128>>>(qkvh, qkvl, bias_table, yh, yl);
    }

    // 3) Output projection -> fp32 out
    {
        dim3 grid(1, M / 128);
        tc_gemm_kernel<<<grid, 256, SM2_TOTAL>>>(yh, yl, wph, wpl, wp_b,
                                                 out, nullptr, nullptr, 256);
    }
}